// round 4
// baseline (speedup 1.0000x reference)
#include <cuda_runtime.h>
#include <math_constants.h>

#define BB 512
#define TT 512
#define KK 64

// 16.7 MB history scratch (argmax index per (b, t, j)), plus per-batch best-last tag.
__device__ unsigned char g_hist[(size_t)BB * TT * KK];
__device__ int g_best[BB];

// ---------------------------------------------------------------------------
// Packed f32x2 helpers (sm_100+). Each half computes the same fl(a+b) as
// scalar FADD.rn -> bit-exact vs reference association (s + t) + e.
// ---------------------------------------------------------------------------
__device__ __forceinline__ unsigned long long addx2(unsigned long long a,
                                                    unsigned long long b) {
    unsigned long long r;
    asm("add.rn.f32x2 %0, %1, %2;" : "=l"(r) : "l"(a), "l"(b));
    return r;
}
__device__ __forceinline__ unsigned long long packf2(float lo, float hi) {
    unsigned long long r;
    asm("mov.b64 %0, {%1, %2};" : "=l"(r) : "f"(lo), "f"(hi));
    return r;
}
__device__ __forceinline__ void unpackf2(unsigned long long v, float& lo, float& hi) {
    asm("mov.b64 {%0, %1}, %2;" : "=f"(lo), "=f"(hi) : "l"(v));
}

// Padded score index: j=32..63 shifted by +2 floats so the c=1 half starts at
// byte 136 (8B aligned, different bank group than c=0's base -> conflict-free
// broadcast pairs).
__device__ __forceinline__ int pidx(int j) { return j + ((j >> 5) << 1); }

// ---------------------------------------------------------------------------
// Forward Viterbi. Block = 128 threads = one batch.
//   thread (j = tid>>1, c = tid&1); c covers prev-tags i in [32c, 32c+32).
//   Candidates v_i = (s_i + trans[i][j]) + e_j via packed f32x2 adds.
//   Argmax: 4 chains of 8 (contiguous, strict >, ascending) -> 3 strict merges
//   -> shfl.xor(1) strict merge (c0 keeps ties = lowest index). Exactly
//   reproduces jnp.argmax first-occurrence semantics.
// ---------------------------------------------------------------------------
__global__ __launch_bounds__(128, 4) void viterbi_forward(
    const float* __restrict__ emissions,   // [B, T, K]
    const int*   __restrict__ mask,        // [B, T]
    const float* __restrict__ start_t,     // [K]
    const float* __restrict__ end_t,       // [K]
    const float* __restrict__ trans)       // [K, K]
{
    const int b   = blockIdx.x;
    const int tid = threadIdx.x;
    const int j   = tid >> 1;
    const int c   = tid & 1;

    __shared__ __align__(16) float sbuf[2][68];
    __shared__ int smask[TT];

    const float* em = emissions + (size_t)b * TT * KK;
    const int*   mk = mask + (size_t)b * TT;

    // Stage mask row once.
    for (int k = tid; k < TT; k += 128) smask[k] = mk[k];

    // Transition half-column trans[32c + k][j] -> 16 packed register pairs.
    unsigned long long tp[16];
#pragma unroll
    for (int q = 0; q < 16; ++q) {
        const int i0 = c * 32 + 2 * q;
        tp[q] = packf2(trans[i0 * KK + j], trans[(i0 + 1) * KK + j]);
    }

    // t = 0 init
    {
        const float s0 = start_t[j] + em[j];
        if (c == 0) sbuf[0][pidx(j)] = s0;
    }

    // Emission prefetch, depth 2.
    float e_cur = em[1 * KK + j];
    float e_nxt = em[2 * KK + j];

    unsigned char* hp = g_hist + ((size_t)b * TT + 1) * KK + j;

    __syncthreads();

    int p = 0;
    for (int t = 1; t < TT; ++t) {
        // branch-free prefetch of step t+2 (clamped; redundant at the tail)
        const int tpf = (t + 2 < TT) ? (t + 2) : (TT - 1);
        const float e_pf = em[tpf * KK + j];

        const unsigned long long ee = packf2(e_cur, e_cur);
        const unsigned long long* sp =
            (const unsigned long long*)((const char*)sbuf[p] + (c ? 136 : 0));

        // 4 chains x 8 candidates (contiguous chunks, ascending, strict >)
        float bst0 = -CUDART_INF_F, bst1 = -CUDART_INF_F,
              bst2 = -CUDART_INF_F, bst3 = -CUDART_INF_F;
        int   bid0 = 0, bid1 = 0, bid2 = 0, bid3 = 0;

#pragma unroll
        for (int q = 0; q < 4; ++q) {   // pair q within each chain
            // chain 0: pairs 0..3 ; chain 1: pairs 4..7 ; etc.
            {
                const unsigned long long v2 = addx2(addx2(sp[q], tp[q]), ee);
                float vl, vh; unpackf2(v2, vl, vh);
                const int ib = c * 32 + 2 * q;
                const bool gl = vl > bst0; bst0 = fmaxf(bst0, vl); bid0 = gl ? ib     : bid0;
                const bool gh = vh > bst0; bst0 = fmaxf(bst0, vh); bid0 = gh ? ib + 1 : bid0;
            }
            {
                const unsigned long long v2 = addx2(addx2(sp[4 + q], tp[4 + q]), ee);
                float vl, vh; unpackf2(v2, vl, vh);
                const int ib = c * 32 + 8 + 2 * q;
                const bool gl = vl > bst1; bst1 = fmaxf(bst1, vl); bid1 = gl ? ib     : bid1;
                const bool gh = vh > bst1; bst1 = fmaxf(bst1, vh); bid1 = gh ? ib + 1 : bid1;
            }
            {
                const unsigned long long v2 = addx2(addx2(sp[8 + q], tp[8 + q]), ee);
                float vl, vh; unpackf2(v2, vl, vh);
                const int ib = c * 32 + 16 + 2 * q;
                const bool gl = vl > bst2; bst2 = fmaxf(bst2, vl); bid2 = gl ? ib     : bid2;
                const bool gh = vh > bst2; bst2 = fmaxf(bst2, vh); bid2 = gh ? ib + 1 : bid2;
            }
            {
                const unsigned long long v2 = addx2(addx2(sp[12 + q], tp[12 + q]), ee);
                float vl, vh; unpackf2(v2, vl, vh);
                const int ib = c * 32 + 24 + 2 * q;
                const bool gl = vl > bst3; bst3 = fmaxf(bst3, vl); bid3 = gl ? ib     : bid3;
                const bool gh = vh > bst3; bst3 = fmaxf(bst3, vh); bid3 = gh ? ib + 1 : bid3;
            }
        }

        // Chain merges: strict > -> lower chunk keeps ties (first-index).
        {
            const bool g1 = bst1 > bst0; bst0 = g1 ? bst1 : bst0; bid0 = g1 ? bid1 : bid0;
            const bool g3 = bst3 > bst2; bst2 = g3 ? bst3 : bst2; bid2 = g3 ? bid3 : bid2;
            const bool g2 = bst2 > bst0; bst0 = g2 ? bst2 : bst0; bid0 = g2 ? bid2 : bid0;
        }

        // Cross-half merge: partner lane (c^1). On c=0, partner holds chunk
        // [32,64) -> strict > keeps first-index ties. (c=1 result unused.)
        {
            const float vo = __shfl_xor_sync(0xFFFFFFFFu, bst0, 1);
            const int   io = __shfl_xor_sync(0xFFFFFFFFu, bid0, 1);
            const bool  go = vo > bst0;
            bst0 = go ? vo : bst0;
            bid0 = go ? io : bid0;
        }

        if (c == 0) {
            // history always records the argmax; mask only gates the score.
            *hp = (unsigned char)bid0;
            const float old = sbuf[p][pidx(j)];
            const float ns  = smask[t] ? bst0 : old;
            sbuf[p ^ 1][pidx(j)] = ns;
        }
        __syncthreads();
        p ^= 1;
        e_cur = e_nxt;
        e_nxt = e_pf;
        hp += KK;
    }

    // Final: add end_transitions, first-index argmax over j (thread 0).
    if (tid == 0) {
        float bv = sbuf[p][pidx(0)] + end_t[0];
        int   bi = 0;
#pragma unroll
        for (int i = 1; i < KK; ++i) {
            const float f = sbuf[p][pidx(i)] + end_t[i];
            if (f > bv) { bv = f; bi = i; }
        }
        g_best[b] = bi;
    }
}

// ---------------------------------------------------------------------------
// Backtrace: one block per batch. Stage the 32KB history slab + mask into
// shared, then one thread walks the dependent chain at LDS latency.
// Output tags written as FLOAT32 (harness output dtype).
// ---------------------------------------------------------------------------
__global__ __launch_bounds__(256) void viterbi_backtrace(
    const int*  __restrict__ mask,   // [B, T]
    float*      __restrict__ out)    // [B, T] float32 tags
{
    const int b = blockIdx.x;
    __shared__ unsigned char h[TT * KK];   // 32 KB
    __shared__ int msk[TT];                // 2 KB

    const uint4* src = (const uint4*)(g_hist + (size_t)b * TT * KK);
    uint4* dst = (uint4*)h;
#pragma unroll 4
    for (int k = threadIdx.x; k < (TT * KK) / 16; k += blockDim.x)
        dst[k] = src[k];
    for (int t = threadIdx.x; t < TT; t += blockDim.x)
        msk[t] = mask[b * TT + t];
    __syncthreads();

    if (threadIdx.x == 0) {
        int tag = g_best[b];
        out[b * TT + (TT - 1)] = (float)tag;
        for (int t = TT - 1; t >= 1; --t) {
            const int prev = h[t * KK + tag];
            tag = msk[t] ? prev : tag;
            out[b * TT + t - 1] = (float)tag;
        }
    }
}

extern "C" void kernel_launch(void* const* d_in, const int* in_sizes, int n_in,
                              void* d_out, int out_size)
{
    // Bind inputs by element count:
    //   16777216 -> emissions, 262144 -> attn_mask, 4096 -> transitions,
    //   64 -> start_transitions (first), end_transitions (second)
    const float* emissions = nullptr;
    const int*   attn_mask = nullptr;
    const float* start_t   = nullptr;
    const float* end_t     = nullptr;
    const float* trans     = nullptr;

    for (int i = 0; i < n_in; ++i) {
        const int sz = in_sizes[i];
        if (sz == BB * TT * KK)      emissions = (const float*)d_in[i];
        else if (sz == BB * TT)      attn_mask = (const int*)d_in[i];
        else if (sz == KK * KK)      trans     = (const float*)d_in[i];
        else if (sz == KK) {
            if (!start_t) start_t = (const float*)d_in[i];
            else          end_t   = (const float*)d_in[i];
        }
    }

    float* out = (float*)d_out;  // [512,512] float32 tag values

    viterbi_forward<<<BB, 128>>>(emissions, attn_mask, start_t, end_t, trans);
    viterbi_backtrace<<<BB, 256>>>(attn_mask, out);
}

// round 5
// speedup vs baseline: 1.3752x; 1.3752x over previous
#include <cuda_runtime.h>
#include <math_constants.h>

#define BB 512
#define TT 512
#define KK 64

// 16.7 MB history scratch (argmax index per (b, t, j)), plus per-batch best-last tag.
__device__ unsigned char g_hist[(size_t)BB * TT * KK];
__device__ int g_best[BB];

// ---------------------------------------------------------------------------
// Forward Viterbi with exact candidate pruning.
//   Block = 64 threads = one batch; thread j owns next-tag j.
//   Live set L(t) = { i : s_i >= smax + (Tmin - Tmax) - margin }.
//   A pruned i satisfies (s_i + t_ij) < (smax + t_imax,j) - margin for every j,
//   with margin (0.05) >> accumulated float rounding, so it can never be the
//   argmax — not even through first-index ties. Survivors are iterated in
//   ascending index order with strict '>', reproducing jnp.argmax exactly.
// ---------------------------------------------------------------------------
__global__ __launch_bounds__(KK, 8) void viterbi_forward(
    const float* __restrict__ emissions,   // [B, T, K]
    const int*   __restrict__ mask,        // [B, T]
    const float* __restrict__ start_t,     // [K]
    const float* __restrict__ end_t,       // [K]
    const float* __restrict__ trans)       // [K, K]
{
    const int b = blockIdx.x;
    const int j = threadIdx.x;

    __shared__ __align__(16) float trans_sh[65 * KK];  // row 64 = sentinel (0)
    __shared__ __align__(16) float s_sh[2][72];        // [64] = -inf sentinel
    __shared__ __align__(16) int   live_sh[72];        // ascending live list + pads
    __shared__ __align__(16) float part_sh[16];
    __shared__ unsigned int ballots[2];
    __shared__ float thrD;                             // (Tmin - Tmax) - margin
    __shared__ int smask[TT];

    const float* em = emissions + (size_t)b * TT * KK;
    const int*   mk = mask + (size_t)b * TT;

    // ---- one-time: trans -> shared, Tmin/Tmax, mask row ----
    float tmn = CUDART_INF_F, tmx = -CUDART_INF_F;
    for (int idx = j; idx < KK * KK; idx += KK) {
        const float v = trans[idx];
        trans_sh[idx] = v;
        tmn = fminf(tmn, v);
        tmx = fmaxf(tmx, v);
    }
    trans_sh[64 * KK + j] = 0.0f;                      // sentinel row
    for (int k = j; k < TT; k += KK) smask[k] = mk[k];

    s_sh[0][j] = tmn;                                  // scratch use
    s_sh[1][j] = tmx;
    __syncthreads();
    if (j == 0) {
        float mn = s_sh[0][0], mx = s_sh[1][0];
#pragma unroll
        for (int i = 1; i < KK; ++i) {
            mn = fminf(mn, s_sh[0][i]);
            mx = fmaxf(mx, s_sh[1][i]);
        }
        thrD = (mn - mx) - 0.05f;
    }
    __syncthreads();

    // ---- init scores ----
    float sreg = start_t[j] + em[j];
    s_sh[0][j] = sreg;
    if (j == 0) { s_sh[0][64] = -CUDART_INF_F; s_sh[1][64] = -CUDART_INF_F; }
    __syncthreads();

    // ---- build initial live list from s_sh[0] ----
    int nl;  // carried in registers across steps
    {
        if (j < 16) {
            const float4 v = *(const float4*)&s_sh[0][4 * j];
            part_sh[j] = fmaxf(fmaxf(v.x, v.y), fmaxf(v.z, v.w));
        }
        __syncthreads();
        const float4 p0 = *(const float4*)&part_sh[0];
        const float4 p1 = *(const float4*)&part_sh[4];
        const float4 p2 = *(const float4*)&part_sh[8];
        const float4 p3 = *(const float4*)&part_sh[12];
        const float m = fmaxf(
            fmaxf(fmaxf(fmaxf(p0.x, p0.y), fmaxf(p0.z, p0.w)),
                  fmaxf(fmaxf(p1.x, p1.y), fmaxf(p1.z, p1.w))),
            fmaxf(fmaxf(fmaxf(p2.x, p2.y), fmaxf(p2.z, p2.w)),
                  fmaxf(fmaxf(p3.x, p3.y), fmaxf(p3.z, p3.w))));
        const float thr = m + thrD;
        const unsigned bal = __ballot_sync(0xFFFFFFFFu, sreg >= thr);
        if ((j & 31) == 0) ballots[j >> 5] = bal;
        __syncthreads();
        const unsigned b0 = ballots[0], b1 = ballots[1];
        nl = __popc(b0) + __popc(b1);
        const unsigned lanemask = (1u << (j & 31)) - 1u;
        const bool liveme = (j < 32) ? ((b0 >> j) & 1u) : ((b1 >> (j - 32)) & 1u);
        const int pos = (j < 32) ? __popc(b0 & lanemask)
                                 : (__popc(b0) + __popc(b1 & lanemask));
        if (liveme) live_sh[pos] = j;
        if (j < 4) live_sh[nl + j] = 64;               // sentinel pads
        __syncthreads();
    }

    // ---- emission prefetch, depth 2 ----
    float e_cur = em[1 * KK + j];
    float e_nxt = em[2 * KK + j];

    unsigned char* hp = g_hist + ((size_t)b * TT + 1) * KK + j;

    int p = 0;
    for (int t = 1; t < TT; ++t) {
        // branch-free prefetch of step t+2
        const int tpf = (t + 2 < TT) ? (t + 2) : (TT - 1);
        const float e_pf = em[tpf * KK + j];

        // ---- phase A: argmax over live prev-tags (ascending, strict >) ----
        const float e = e_cur;
        const float* scur = s_sh[p];
        float bst = -CUDART_INF_F;
        int   bid = 0;
        const int ng = (nl + 3) >> 2;
        const int4* lv = (const int4*)live_sh;
        for (int g = 0; g < ng; ++g) {
            const int4 iv = lv[g];
            const float sa = scur[iv.x], sb = scur[iv.y];
            const float sc = scur[iv.z], sd = scur[iv.w];
            const float ta = trans_sh[iv.x * KK + j];
            const float tb = trans_sh[iv.y * KK + j];
            const float tc = trans_sh[iv.z * KK + j];
            const float td = trans_sh[iv.w * KK + j];
            const float va = (sa + ta) + e;
            const float vb = (sb + tb) + e;
            const float vc = (sc + tc) + e;
            const float vd = (sd + td) + e;
            if (va > bst) { bst = va; bid = iv.x; }
            if (vb > bst) { bst = vb; bid = iv.y; }
            if (vc > bst) { bst = vc; bid = iv.z; }
            if (vd > bst) { bst = vd; bid = iv.w; }
        }

        *hp = (unsigned char)bid;                      // history (always)
        const float ns = smask[t] ? bst : sreg;        // mask gates score only
        sreg = ns;
        s_sh[p ^ 1][j] = ns;
        __syncthreads();

        // ---- phase B: rebuild live list for next step ----
        if (j < 16) {
            const float4 v = *(const float4*)&s_sh[p ^ 1][4 * j];
            part_sh[j] = fmaxf(fmaxf(v.x, v.y), fmaxf(v.z, v.w));
        }
        __syncthreads();
        {
            const float4 p0 = *(const float4*)&part_sh[0];
            const float4 p1 = *(const float4*)&part_sh[4];
            const float4 p2 = *(const float4*)&part_sh[8];
            const float4 p3 = *(const float4*)&part_sh[12];
            const float m = fmaxf(
                fmaxf(fmaxf(fmaxf(p0.x, p0.y), fmaxf(p0.z, p0.w)),
                      fmaxf(fmaxf(p1.x, p1.y), fmaxf(p1.z, p1.w))),
                fmaxf(fmaxf(fmaxf(p2.x, p2.y), fmaxf(p2.z, p2.w)),
                      fmaxf(fmaxf(p3.x, p3.y), fmaxf(p3.z, p3.w))));
            const float thr = m + thrD;
            const unsigned bal = __ballot_sync(0xFFFFFFFFu, sreg >= thr);
            if ((j & 31) == 0) ballots[j >> 5] = bal;
        }
        __syncthreads();
        {
            const unsigned b0 = ballots[0], b1 = ballots[1];
            nl = __popc(b0) + __popc(b1);
            const unsigned lanemask = (1u << (j & 31)) - 1u;
            const bool liveme = (j < 32) ? ((b0 >> j) & 1u)
                                         : ((b1 >> (j - 32)) & 1u);
            const int pos = (j < 32) ? __popc(b0 & lanemask)
                                     : (__popc(b0) + __popc(b1 & lanemask));
            if (liveme) live_sh[pos] = j;
            if (j < 4) live_sh[nl + j] = 64;           // sentinel pads
        }
        __syncthreads();

        p ^= 1;
        e_cur = e_nxt;
        e_nxt = e_pf;
        hp += KK;
    }

    // ---- final: + end_transitions, first-index argmax over j ----
    if (j == 0) {
        float bv = s_sh[p][0] + end_t[0];
        int   bi = 0;
#pragma unroll
        for (int i = 1; i < KK; ++i) {
            const float f = s_sh[p][i] + end_t[i];
            if (f > bv) { bv = f; bi = i; }
        }
        g_best[b] = bi;
    }
}

// ---------------------------------------------------------------------------
// Backtrace: one block per batch. Stage the 32KB history slab + mask into
// shared, then one thread walks the dependent chain at LDS latency.
// Output tags written as FLOAT32 (harness output dtype).
// ---------------------------------------------------------------------------
__global__ __launch_bounds__(256) void viterbi_backtrace(
    const int*  __restrict__ mask,   // [B, T]
    float*      __restrict__ out)    // [B, T] float32 tags
{
    const int b = blockIdx.x;
    __shared__ unsigned char h[TT * KK];   // 32 KB
    __shared__ int msk[TT];                // 2 KB

    const uint4* src = (const uint4*)(g_hist + (size_t)b * TT * KK);
    uint4* dst = (uint4*)h;
#pragma unroll 4
    for (int k = threadIdx.x; k < (TT * KK) / 16; k += blockDim.x)
        dst[k] = src[k];
    for (int t = threadIdx.x; t < TT; t += blockDim.x)
        msk[t] = mask[b * TT + t];
    __syncthreads();

    if (threadIdx.x == 0) {
        int tag = g_best[b];
        out[b * TT + (TT - 1)] = (float)tag;
        for (int t = TT - 1; t >= 1; --t) {
            const int prev = h[t * KK + tag];
            tag = msk[t] ? prev : tag;
            out[b * TT + t - 1] = (float)tag;
        }
    }
}

extern "C" void kernel_launch(void* const* d_in, const int* in_sizes, int n_in,
                              void* d_out, int out_size)
{
    // Bind inputs by element count:
    //   16777216 -> emissions, 262144 -> attn_mask, 4096 -> transitions,
    //   64 -> start_transitions (first), end_transitions (second)
    const float* emissions = nullptr;
    const int*   attn_mask = nullptr;
    const float* start_t   = nullptr;
    const float* end_t     = nullptr;
    const float* trans     = nullptr;

    for (int i = 0; i < n_in; ++i) {
        const int sz = in_sizes[i];
        if (sz == BB * TT * KK)      emissions = (const float*)d_in[i];
        else if (sz == BB * TT)      attn_mask = (const int*)d_in[i];
        else if (sz == KK * KK)      trans     = (const float*)d_in[i];
        else if (sz == KK) {
            if (!start_t) start_t = (const float*)d_in[i];
            else          end_t   = (const float*)d_in[i];
        }
    }

    float* out = (float*)d_out;  // [512,512] float32 tag values

    viterbi_forward<<<BB, KK>>>(emissions, attn_mask, start_t, end_t, trans);
    viterbi_backtrace<<<BB, 256>>>(attn_mask, out);
}